// round 16
// baseline (speedup 1.0000x reference)
#include <cuda_runtime.h>
#include <cuda_bf16.h>
#include <cstdint>
#include <cstddef>

#define S_LEN   2048
#define D_MODEL 4096
#define NH      32
#define NKV     8
#define HD      128
#define KVD     (NKV * HD)     // 1024
#define QKVW    (D_MODEL + 2 * KVD)   // 6144 combined QKV width

// ---------------------------------------------------------------------------
// Scratch (__device__ globals; no allocations allowed anywhere).
// ---------------------------------------------------------------------------
static __device__ __nv_bfloat16 g_xhi[S_LEN * D_MODEL],  g_xlo[S_LEN * D_MODEL];
static __device__ __nv_bfloat16 g_whi[D_MODEL * QKVW],   g_wlo[D_MODEL * QKVW];   // wq|wk|wv
static __device__ __nv_bfloat16 g_wohi[D_MODEL * D_MODEL], g_wolo[D_MODEL * D_MODEL];
static __device__ __nv_bfloat16 g_qkvhi[S_LEN * QKVW],   g_qkvlo[S_LEN * QKVW];   // q|k|v (roped)
static __device__ __nv_bfloat16 g_ohi[S_LEN * D_MODEL],  g_olo[S_LEN * D_MODEL];

// ---------------------------------------------------------------------------
// Helpers
// ---------------------------------------------------------------------------
__device__ __forceinline__ uint32_t s2u(const void* p) {
    return (uint32_t)__cvta_generic_to_shared(p);
}
__device__ __forceinline__ void cpa(uint32_t s, const void* g) {
    asm volatile("cp.async.cg.shared.global [%0], [%1], 16;\n" :: "r"(s), "l"(g));
}
__device__ __forceinline__ void ldsm4(uint32_t r[4], uint32_t a) {
    asm volatile("ldmatrix.sync.aligned.m8n8.x4.shared.b16 {%0,%1,%2,%3}, [%4];"
                 : "=r"(r[0]), "=r"(r[1]), "=r"(r[2]), "=r"(r[3]) : "r"(a));
}
__device__ __forceinline__ void ldsm4t(uint32_t r[4], uint32_t a) {
    asm volatile("ldmatrix.sync.aligned.m8n8.x4.trans.shared.b16 {%0,%1,%2,%3}, [%4];"
                 : "=r"(r[0]), "=r"(r[1]), "=r"(r[2]), "=r"(r[3]) : "r"(a));
}
__device__ __forceinline__ void mma16816(float c[4], const uint32_t a[4], const uint32_t b[2]) {
    asm volatile(
        "mma.sync.aligned.m16n8k16.row.col.f32.bf16.bf16.f32 "
        "{%0,%1,%2,%3}, {%4,%5,%6,%7}, {%8,%9}, {%0,%1,%2,%3};"
        : "+f"(c[0]), "+f"(c[1]), "+f"(c[2]), "+f"(c[3])
        : "r"(a[0]), "r"(a[1]), "r"(a[2]), "r"(a[3]), "r"(b[0]), "r"(b[1]));
}
// Pack (a,b) -> bf16x2 hi word + residual bf16x2 lo word.
__device__ __forceinline__ void pack2(float a, float b, uint32_t& hi, uint32_t& lo) {
    uint32_t hpk;
    asm("cvt.rn.bf16x2.f32 %0, %1, %2;" : "=r"(hpk) : "f"(b), "f"(a));
    const float ra = a - __uint_as_float(hpk << 16);
    const float rb = b - __uint_as_float(hpk & 0xffff0000u);
    uint32_t lpk;
    asm("cvt.rn.bf16x2.f32 %0, %1, %2;" : "=r"(lpk) : "f"(rb), "f"(ra));
    hi = hpk; lo = lpk;
}

// ---------------------------------------------------------------------------
// Split fp32 -> (bf16 hi, bf16 lo) with strided (column-offset) output.
// Units of 4 elements. i -> row = i/inw4, col = i%inw4;
// out index = row*outs4 + colo4 + col.
// ---------------------------------------------------------------------------
__global__ void split_k(const float* __restrict__ in, __nv_bfloat16* __restrict__ hi,
                        __nv_bfloat16* __restrict__ lo, int n4, int inw4, int outs4, int colo4)
{
    const int i = blockIdx.x * 256 + threadIdx.x;
    if (i >= n4) return;
    const float4 v = ((const float4*)in)[i];
    const float x[4] = {v.x, v.y, v.z, v.w};
    union { __nv_bfloat16 h[4]; uint2 u; } H, L;
    #pragma unroll
    for (int k = 0; k < 4; ++k) {
        H.h[k] = __float2bfloat16(x[k]);
        L.h[k] = __float2bfloat16(x[k] - __bfloat162float(H.h[k]));
    }
    const int r = i / inw4, c = i - r * inw4;
    const size_t oi = (size_t)r * outs4 + colo4 + c;
    ((uint2*)hi)[oi] = H.u;
    ((uint2*)lo)[oi] = L.u;
}

// ---------------------------------------------------------------------------
// Tensor-core GEMM, 2-term split inputs: C = Ah*Bh + Ah*Bl + Al*Bh (fp32 acc).
// CTA tile 256x128, warp tile 64x64 (8 warps, 4m x 2n), K-chunk 32,
// 3-stage cp.async pipeline (wait_group 1). Optional RoPE epilogue (cols <
// ropeLim); SPLITOUT writes bf16 hi/lo pair, else fp32.
// A: [M,K] row-major stride K. B: [K, ldbc]. C: [M, ldbc].
// ---------------------------------------------------------------------------
#define ST_A (256 * 40)
#define ST_B (32 * 136)
#define GEMM_SMEM (3 * (2 * ST_A + 2 * ST_B) * 2)   // 175104 bytes

template <bool ROPE, bool SPLITOUT>
__global__ void __launch_bounds__(256, 1) gemm_mma(
    const __nv_bfloat16* __restrict__ Ah, const __nv_bfloat16* __restrict__ Al,
    const __nv_bfloat16* __restrict__ Bh, const __nv_bfloat16* __restrict__ Bl,
    float* __restrict__ C, __nv_bfloat16* __restrict__ Chi, __nv_bfloat16* __restrict__ Clo,
    int K, int ldbc, int ropeLim,
    const float* __restrict__ fc, const float* __restrict__ fs)
{
    extern __shared__ __nv_bfloat16 smem[];
    __nv_bfloat16* As_h = smem;                    // [3][256][40]
    __nv_bfloat16* As_l = As_h + 3 * ST_A;
    __nv_bfloat16* Bs_h = As_l + 3 * ST_A;         // [3][32][136]
    __nv_bfloat16* Bs_l = Bs_h + 3 * ST_B;

    const int tid  = threadIdx.x;
    const int lane = tid & 31;
    const int wid  = tid >> 5;
    const int wm   = wid & 3;            // 4 warps along M (64 rows each)
    const int wn   = wid >> 2;           // 2 warps along N (64 cols each)
    const int row0 = blockIdx.y * 256;
    const int n0   = blockIdx.x * 128;

    auto prefetch = [&](int t) {
        const int sl = t % 3;
        const int k0 = t * 32;
        #pragma unroll
        for (int p = 0; p < 4; ++p) {                 // A: 256x32
            const int e = tid + p * 256;
            const int r = e >> 2, c = (e & 3) * 8;
            const size_t g = (size_t)(row0 + r) * K + k0 + c;
            const int so = sl * ST_A + r * 40 + c;
            cpa(s2u(As_h + so), Ah + g);
            cpa(s2u(As_l + so), Al + g);
        }
        #pragma unroll
        for (int p = 0; p < 2; ++p) {                 // B: 32x128
            const int e = tid + p * 256;
            const int r = e >> 4, c = (e & 15) * 8;
            const size_t g = (size_t)(k0 + r) * ldbc + n0 + c;
            const int so = sl * ST_B + r * 136 + c;
            cpa(s2u(Bs_h + so), Bh + g);
            cpa(s2u(Bs_l + so), Bl + g);
        }
        asm volatile("cp.async.commit_group;\n");
    };

    float acc[4][8][4];
    #pragma unroll
    for (int i = 0; i < 4; ++i)
        #pragma unroll
        for (int j = 0; j < 8; ++j)
            #pragma unroll
            for (int q = 0; q < 4; ++q) acc[i][j][q] = 0.f;

    const int T = K / 32;
    prefetch(0);
    prefetch(1);

    for (int t = 0; t < T; ++t) {
        asm volatile("cp.async.wait_group 1;\n");
        __syncthreads();
        if (t + 2 < T) prefetch(t + 2);

        const int sl = t % 3;
        const __nv_bfloat16* Abh = As_h + sl * ST_A;
        const __nv_bfloat16* Abl = As_l + sl * ST_A;
        const __nv_bfloat16* Bbh = Bs_h + sl * ST_B;
        const __nv_bfloat16* Bbl = Bs_l + sl * ST_B;

        #pragma unroll
        for (int kk = 0; kk < 2; ++kk) {
            uint32_t ah[4][4], al[4][4];
            const int cc = kk * 16 + ((lane >> 4) << 3);
            #pragma unroll
            for (int i = 0; i < 4; ++i) {
                const int rr = wm * 64 + i * 16 + (lane & 15);
                ldsm4(ah[i], s2u(Abh + rr * 40 + cc));
                ldsm4(al[i], s2u(Abl + rr * 40 + cc));
            }
            #pragma unroll
            for (int jp = 0; jp < 4; ++jp) {
                const int rr = kk * 16 + (lane & 15);
                const int cb = wn * 64 + jp * 16 + ((lane >> 4) << 3);
                uint32_t r4[4], s4[4];
                ldsm4t(r4, s2u(Bbh + rr * 136 + cb));
                ldsm4t(s4, s2u(Bbl + rr * 136 + cb));
                uint32_t bh0[2] = {r4[0], r4[1]}, bh1[2] = {r4[2], r4[3]};
                uint32_t bl0[2] = {s4[0], s4[1]}, bl1[2] = {s4[2], s4[3]};
                #pragma unroll
                for (int i = 0; i < 4; ++i) {
                    mma16816(acc[i][2*jp],   ah[i], bh0);
                    mma16816(acc[i][2*jp],   ah[i], bl0);
                    mma16816(acc[i][2*jp],   al[i], bh0);
                    mma16816(acc[i][2*jp+1], ah[i], bh1);
                    mma16816(acc[i][2*jp+1], ah[i], bl1);
                    mma16816(acc[i][2*jp+1], al[i], bh1);
                }
            }
        }
        __syncthreads();
    }

    const int g  = lane >> 2;
    const int tq = lane & 3;
    #pragma unroll
    for (int i = 0; i < 4; ++i) {
        const int rbase = row0 + wm * 64 + i * 16 + g;
        #pragma unroll
        for (int j = 0; j < 8; ++j) {
            const int col = n0 + wn * 64 + j * 8 + tq * 2;
            float v0 = acc[i][j][0], v1 = acc[i][j][1];
            float v2 = acc[i][j][2], v3 = acc[i][j][3];
            if (ROPE && col < ropeLim) {
                const int pi = (col & (HD - 1)) >> 1;
                const float c0 = fc[rbase * (HD/2) + pi];
                const float s0 = fs[rbase * (HD/2) + pi];
                const float c1 = fc[(rbase + 8) * (HD/2) + pi];
                const float s1 = fs[(rbase + 8) * (HD/2) + pi];
                float t0 = v0, t1 = v1;
                v0 = t0 * c0 - t1 * s0;  v1 = t0 * s0 + t1 * c0;
                t0 = v2; t1 = v3;
                v2 = t0 * c1 - t1 * s1;  v3 = t0 * s1 + t1 * c1;
            }
            if (SPLITOUT) {
                uint32_t hp, lp;
                pack2(v0, v1, hp, lp);
                *(uint32_t*)&Chi[(size_t)rbase * ldbc + col] = hp;
                *(uint32_t*)&Clo[(size_t)rbase * ldbc + col] = lp;
                pack2(v2, v3, hp, lp);
                *(uint32_t*)&Chi[(size_t)(rbase + 8) * ldbc + col] = hp;
                *(uint32_t*)&Clo[(size_t)(rbase + 8) * ldbc + col] = lp;
            } else {
                *(float2*)&C[(size_t)rbase * ldbc + col]       = make_float2(v0, v1);
                *(float2*)&C[(size_t)(rbase + 8) * ldbc + col] = make_float2(v2, v3);
            }
        }
    }
}

// ---------------------------------------------------------------------------
// Tensorized flash attention (proven R14 version; Q/K/V from combined qkv
// buffer with row stride QKVW). CTA = (head, 64 q rows), 4 warps.
// ---------------------------------------------------------------------------
#define ATTN_SMEM (6 * 64 * 136 * 2)

__global__ void __launch_bounds__(128, 2) attn_mma(
    const __nv_bfloat16* __restrict__ qkvhi, const __nv_bfloat16* __restrict__ qkvlo,
    __nv_bfloat16* __restrict__ ohi, __nv_bfloat16* __restrict__ olo)
{
    extern __shared__ __nv_bfloat16 as_[];
    __nv_bfloat16* Qh = as_;
    __nv_bfloat16* Ql = Qh + 64 * 136;
    __nv_bfloat16* Kh = Ql + 64 * 136;
    __nv_bfloat16* Kl = Kh + 64 * 136;
    __nv_bfloat16* Vh = Kl + 64 * 136;
    __nv_bfloat16* Vl = Vh + 64 * 136;

    const int tid  = threadIdx.x;
    const int lane = tid & 31;
    const int w    = tid >> 5;
    const int qt   = (int)gridDim.x - 1 - (int)blockIdx.x;
    const int h    = blockIdx.y;
    const int hk   = h >> 2;
    const int q0   = qt * 64;
    const int g    = lane >> 2;
    const int qd   = lane & 3;
    const int row0g = q0 + w * 16 + g;
    const int row1g = row0g + 8;
    const float scale = 0.08838834764831845f;

    #pragma unroll
    for (int p = 0; p < 8; ++p) {
        const int e = tid + p * 128, r = e >> 4, c8 = (e & 15) * 8;
        const size_t go = (size_t)(q0 + r) * QKVW + h * HD + c8;
        cpa(s2u(Qh + r * 136 + c8), qkvhi + go);
        cpa(s2u(Ql + r * 136 + c8), qkvlo + go);
    }
    asm volatile("cp.async.commit_group;\n");

    float accO[16][4];
    #pragma unroll
    for (int d = 0; d < 16; ++d)
        #pragma unroll
        for (int e = 0; e < 4; ++e) accO[d][e] = 0.f;
    float m0 = -1e30f, m1 = -1e30f, l0 = 0.f, l1 = 0.f;

    for (int kt = 0; kt <= qt; ++kt) {
        __syncthreads();
        #pragma unroll
        for (int p = 0; p < 8; ++p) {
            const int e = tid + p * 128, r = e >> 4, c8 = (e & 15) * 8;
            const size_t gk = (size_t)(kt * 64 + r) * QKVW + D_MODEL + hk * HD + c8;
            const size_t gv = gk + KVD;
            const int so = r * 136 + c8;
            cpa(s2u(Kh + so), qkvhi + gk);
            cpa(s2u(Kl + so), qkvlo + gk);
            cpa(s2u(Vh + so), qkvhi + gv);
            cpa(s2u(Vl + so), qkvlo + gv);
        }
        asm volatile("cp.async.commit_group;\ncp.async.wait_group 0;\n");
        __syncthreads();

        float sc[8][4];
        #pragma unroll
        for (int t = 0; t < 8; ++t)
            #pragma unroll
            for (int e = 0; e < 4; ++e) sc[t][e] = 0.f;

        #pragma unroll
        for (int kk = 0; kk < 8; ++kk) {
            uint32_t qa[4], qb[4];
            const int ra = w * 16 + (lane & 15);
            const int cc = kk * 16 + ((lane >> 4) << 3);
            ldsm4(qa, s2u(Qh + ra * 136 + cc));
            ldsm4(qb, s2u(Ql + ra * 136 + cc));
            #pragma unroll
            for (int jp = 0; jp < 4; ++jp) {
                uint32_t r4[4], s4[4];
                const int rb = jp * 16 + (lane & 15);
                ldsm4(r4, s2u(Kh + rb * 136 + cc));
                ldsm4(s4, s2u(Kl + rb * 136 + cc));
                uint32_t bh0[2] = {r4[0], r4[2]}, bh1[2] = {r4[1], r4[3]};
                uint32_t bl0[2] = {s4[0], s4[2]}, bl1[2] = {s4[1], s4[3]};
                mma16816(sc[2*jp],   qa, bh0);
                mma16816(sc[2*jp],   qa, bl0);
                mma16816(sc[2*jp],   qb, bh0);
                mma16816(sc[2*jp+1], qa, bh1);
                mma16816(sc[2*jp+1], qa, bl1);
                mma16816(sc[2*jp+1], qb, bh1);
            }
        }

        const bool diag = (kt == qt);
        #pragma unroll
        for (int t = 0; t < 8; ++t)
            #pragma unroll
            for (int e = 0; e < 4; ++e) {
                float v = sc[t][e] * scale;
                if (diag) {
                    const int col = kt * 64 + t * 8 + qd * 2 + (e & 1);
                    const int row = (e < 2) ? row0g : row1g;
                    if (col > row) v = -1e30f;
                }
                sc[t][e] = v;
            }

        float tm0 = -1e30f, tm1 = -1e30f;
        #pragma unroll
        for (int t = 0; t < 8; ++t) {
            tm0 = fmaxf(tm0, fmaxf(sc[t][0], sc[t][1]));
            tm1 = fmaxf(tm1, fmaxf(sc[t][2], sc[t][3]));
        }
        #pragma unroll
        for (int o = 1; o <= 2; o <<= 1) {
            tm0 = fmaxf(tm0, __shfl_xor_sync(0xffffffffu, tm0, o));
            tm1 = fmaxf(tm1, __shfl_xor_sync(0xffffffffu, tm1, o));
        }
        const float m0n = fmaxf(m0, tm0), m1n = fmaxf(m1, tm1);
        const float f0 = __expf(m0 - m0n), f1 = __expf(m1 - m1n);

        float rs0 = 0.f, rs1 = 0.f;
        #pragma unroll
        for (int t = 0; t < 8; ++t) {
            sc[t][0] = __expf(sc[t][0] - m0n); rs0 += sc[t][0];
            sc[t][1] = __expf(sc[t][1] - m0n); rs0 += sc[t][1];
            sc[t][2] = __expf(sc[t][2] - m1n); rs1 += sc[t][2];
            sc[t][3] = __expf(sc[t][3] - m1n); rs1 += sc[t][3];
        }
        #pragma unroll
        for (int o = 1; o <= 2; o <<= 1) {
            rs0 += __shfl_xor_sync(0xffffffffu, rs0, o);
            rs1 += __shfl_xor_sync(0xffffffffu, rs1, o);
        }
        l0 = l0 * f0 + rs0;  l1 = l1 * f1 + rs1;
        m0 = m0n;            m1 = m1n;

        #pragma unroll
        for (int d = 0; d < 16; ++d) {
            accO[d][0] *= f0; accO[d][1] *= f0;
            accO[d][2] *= f1; accO[d][3] *= f1;
        }

        uint32_t ph[4][4], pl[4][4];
        #pragma unroll
        for (int j = 0; j < 4; ++j) {
            pack2(sc[2*j][0],   sc[2*j][1],   ph[j][0], pl[j][0]);
            pack2(sc[2*j][2],   sc[2*j][3],   ph[j][1], pl[j][1]);
            pack2(sc[2*j+1][0], sc[2*j+1][1], ph[j][2], pl[j][2]);
            pack2(sc[2*j+1][2], sc[2*j+1][3], ph[j][3], pl[j][3]);
        }

        #pragma unroll
        for (int dp = 0; dp < 8; ++dp) {
            const int ccv = dp * 16 + ((lane >> 4) << 3);
            #pragma unroll
            for (int j = 0; j < 4; ++j) {
                uint32_t r4[4], s4[4];
                const int rv = j * 16 + (lane & 15);
                ldsm4t(r4, s2u(Vh + rv * 136 + ccv));
                ldsm4t(s4, s2u(Vl + rv * 136 + ccv));
                uint32_t bh0[2] = {r4[0], r4[1]}, bh1[2] = {r4[2], r4[3]};
                uint32_t bl0[2] = {s4[0], s4[1]}, bl1[2] = {s4[2], s4[3]};
                mma16816(accO[2*dp],   ph[j], bh0);
                mma16816(accO[2*dp],   ph[j], bl0);
                mma16816(accO[2*dp],   pl[j], bh0);
                mma16816(accO[2*dp+1], ph[j], bh1);
                mma16816(accO[2*dp+1], ph[j], bl1);
                mma16816(accO[2*dp+1], pl[j], bh1);
            }
        }
    }

    const float i0 = 1.f / l0, i1 = 1.f / l1;
    #pragma unroll
    for (int dt = 0; dt < 16; ++dt) {
        const int col = h * HD + dt * 8 + qd * 2;
        uint32_t hp, lp;
        pack2(accO[dt][0] * i0, accO[dt][1] * i0, hp, lp);
        *(uint32_t*)&ohi[(size_t)row0g * D_MODEL + col] = hp;
        *(uint32_t*)&olo[(size_t)row0g * D_MODEL + col] = lp;
        pack2(accO[dt][2] * i1, accO[dt][3] * i1, hp, lp);
        *(uint32_t*)&ohi[(size_t)row1g * D_MODEL + col] = hp;
        *(uint32_t*)&olo[(size_t)row1g * D_MODEL + col] = lp;
    }
}

// ---------------------------------------------------------------------------
// Launch. Graph-capturable, allocation-free.
// ---------------------------------------------------------------------------
extern "C" void kernel_launch(void* const* d_in, const int* in_sizes, int n_in,
                              void* d_out, int out_size)
{
    const float* x  = (const float*)d_in[0];
    const float* wq = (const float*)d_in[1];
    const float* wk = (const float*)d_in[2];
    const float* wv = (const float*)d_in[3];
    const float* wo = (const float*)d_in[4];
    const float* fc = (const float*)d_in[5];
    const float* fs = (const float*)d_in[6];
    float* out = (float*)d_out;

    __nv_bfloat16 *xhi, *xlo, *whi, *wlo, *wohi, *wolo, *qkvhi, *qkvlo, *ohi, *olo;
    cudaGetSymbolAddress((void**)&xhi, g_xhi);     cudaGetSymbolAddress((void**)&xlo, g_xlo);
    cudaGetSymbolAddress((void**)&whi, g_whi);     cudaGetSymbolAddress((void**)&wlo, g_wlo);
    cudaGetSymbolAddress((void**)&wohi, g_wohi);   cudaGetSymbolAddress((void**)&wolo, g_wolo);
    cudaGetSymbolAddress((void**)&qkvhi, g_qkvhi); cudaGetSymbolAddress((void**)&qkvlo, g_qkvlo);
    cudaGetSymbolAddress((void**)&ohi, g_ohi);     cudaGetSymbolAddress((void**)&olo, g_olo);

    cudaFuncSetAttribute((const void*)gemm_mma<true,  true >, cudaFuncAttributeMaxDynamicSharedMemorySize, GEMM_SMEM);
    cudaFuncSetAttribute((const void*)gemm_mma<false, false>, cudaFuncAttributeMaxDynamicSharedMemorySize, GEMM_SMEM);
    cudaFuncSetAttribute((const void*)attn_mma, cudaFuncAttributeMaxDynamicSharedMemorySize, ATTN_SMEM);

    // Splits: x plain; wq/wk/wv strided into combined [4096 x 6144]; wo plain.
    {
        int n4 = S_LEN * D_MODEL / 4;
        split_k<<<(n4 + 255) / 256, 256>>>(x, xhi, xlo, n4, 1024, 1024, 0);
        n4 = D_MODEL * D_MODEL / 4;
        split_k<<<(n4 + 255) / 256, 256>>>(wq, whi, wlo, n4, 1024, QKVW / 4, 0);
        split_k<<<(n4 + 255) / 256, 256>>>(wo, wohi, wolo, n4, 1024, 1024, 0);
        n4 = D_MODEL * KVD / 4;
        split_k<<<(n4 + 255) / 256, 256>>>(wk, whi, wlo, n4, 256, QKVW / 4, 1024);
        split_k<<<(n4 + 255) / 256, 256>>>(wv, whi, wlo, n4, 256, QKVW / 4, 1280);
    }

    dim3 blk(256);
    // QKV = x @ [wq|wk|wv]  (+RoPE on cols < 5120), split bf16 output
    gemm_mma<true, true ><<<dim3(QKVW / 128, S_LEN / 256), blk, GEMM_SMEM>>>(
        xhi, xlo, whi, wlo, nullptr, qkvhi, qkvlo,
        D_MODEL, QKVW, D_MODEL + KVD, fc, fs);
    // Attention (tensorized), split output
    attn_mma<<<dim3(S_LEN / 64, NH), dim3(128), ATTN_SMEM>>>(qkvhi, qkvlo, ohi, olo);
    // out = o @ wo, fp32 output
    gemm_mma<false, false><<<dim3(D_MODEL / 128, S_LEN / 256), blk, GEMM_SMEM>>>(
        ohi, olo, wohi, wolo, out, nullptr, nullptr,
        D_MODEL, D_MODEL, 0, nullptr, nullptr);
}